// round 2
// baseline (speedup 1.0000x reference)
#include <cuda_runtime.h>
#include <cuda_bf16.h>
#include <cstdint>

// ---------------------------------------------------------------------------
// RNN-Transducer: 2x proj-LSTM encoder + 2x proj-LSTM decoder + joint tanh.
// B=8, T=256, U=64, D_enc=80, D_dec=256, H=1024, P=512, V=256.
// ---------------------------------------------------------------------------

#define Bb   8
#define Tt   256
#define Uu   64
#define Hh   1024
#define Pp   512
#define G4   4096
#define Vv   256
#define NBLK 128

// -------------------- scratch (device globals; no allocation) --------------
__device__ float g_xg  [2048 * 4096];      // gate preacts for current layer
__device__ float g_enc0[2048 * 512];
__device__ float g_enc1[2048 * 512];
__device__ float g_dec0[512  * 512];
__device__ float g_dec1[512  * 512];
__device__ float g_ej  [2048 * 256];
__device__ float g_gj  [512  * 256];
__device__ float g_hbuf[8 * 1024];

// -------------------- grid barrier (generation counter) --------------------
__device__ unsigned g_bar_cnt = 0;
__device__ volatile unsigned g_bar_gen = 0;

__device__ __forceinline__ void grid_bar() {
    __syncthreads();
    if (threadIdx.x == 0) {
        __threadfence();
        unsigned gen = g_bar_gen;
        if (atomicAdd(&g_bar_cnt, 1u) == NBLK - 1) {
            g_bar_cnt = 0;
            __threadfence();
            g_bar_gen = gen + 1;
        } else {
            while (g_bar_gen == gen) { }
            __threadfence();
        }
    }
    __syncthreads();
}

__device__ __forceinline__ float sigf(float x) {
    return 1.0f / (1.0f + __expf(-x));
}

// -------------------- generic GEMM: C[n,N] = A[n,K] @ W[K,N] (+bias) -------
// Requires n%64==0, K%16==0, N%64==0 (true for all calls here).
__global__ __launch_bounds__(256) void gemm_bias_kernel(
    const float* __restrict__ A, const float* __restrict__ W,
    const float* __restrict__ bias, float* __restrict__ C,
    int n, int K, int N)
{
    __shared__ float As[16][65];   // [k][m], padded
    __shared__ float Ws[16][64];   // [k][n]
    const int bn = blockIdx.x * 64;
    const int bm = blockIdx.y * 64;
    const int tid = threadIdx.x;
    const int tm = tid >> 4, tn = tid & 15;

    float acc[4][4];
#pragma unroll
    for (int x = 0; x < 4; ++x)
#pragma unroll
        for (int y = 0; y < 4; ++y) acc[x][y] = 0.f;

    for (int k0 = 0; k0 < K; k0 += 16) {
#pragma unroll
        for (int i = tid; i < 1024; i += 256) {
            int r = i >> 4, c = i & 15;                   // r: row in tile, c: k
            As[c][r] = A[(size_t)(bm + r) * K + k0 + c];
        }
#pragma unroll
        for (int i = tid; i < 1024; i += 256) {
            int r = i >> 6, c = i & 63;                   // r: k, c: col in tile
            Ws[r][c] = W[(size_t)(k0 + r) * N + bn + c];
        }
        __syncthreads();
#pragma unroll
        for (int kk = 0; kk < 16; ++kk) {
            float a[4], b[4];
#pragma unroll
            for (int x = 0; x < 4; ++x) a[x] = As[kk][tm * 4 + x];
#pragma unroll
            for (int y = 0; y < 4; ++y) b[y] = Ws[kk][tn * 4 + y];
#pragma unroll
            for (int x = 0; x < 4; ++x)
#pragma unroll
                for (int y = 0; y < 4; ++y) acc[x][y] += a[x] * b[y];
        }
        __syncthreads();
    }

    float bv[4];
#pragma unroll
    for (int y = 0; y < 4; ++y) bv[y] = bias ? bias[bn + tn * 4 + y] : 0.f;
#pragma unroll
    for (int x = 0; x < 4; ++x) {
        size_t row = (size_t)(bm + tm * 4 + x);
#pragma unroll
        for (int y = 0; y < 4; ++y)
            C[row * N + bn + tn * 4 + y] = acc[x][y] + bv[y];
    }
}

// -------------------- persistent projected-LSTM layer -----------------------
// Block blk owns h-units [blk*8, blk*8+8) and p-cols [blk*4, blk*4+4).
// SMEM layout (floats):
//   Wh_sh [32][516]  col-major padded   16512
//   Wp_sh [4][1028]  p-major padded      4112
//   m_sh  [8][512]                       4096
//   h_sh  [8][1028]  padded              8224
//   g_sh  [8][32]                         256
//   c_sh  [64]                             64
//   red   [8][32]                         256
constexpr int OFF_WH = 0;
constexpr int OFF_WP = OFF_WH + 32 * 516;
constexpr int OFF_M  = OFF_WP + 4 * 1028;
constexpr int OFF_H  = OFF_M  + 8 * 512;
constexpr int OFF_G  = OFF_H  + 8 * 1028;
constexpr int OFF_C  = OFF_G  + 256;
constexpr int OFF_R  = OFF_C  + 64;
constexpr int SMEM_FLOATS = OFF_R + 256;
constexpr int SMEM_BYTES  = SMEM_FLOATS * 4;   // 134,080 B

__global__ __launch_bounds__(256, 1) void lstm_layer_kernel(
    const float* __restrict__ xg,   // [B*T, 4096]
    const float* __restrict__ Wh,   // [512, 4096]
    const float* __restrict__ Wp,   // [1024, 512]
    float* __restrict__ seq_out,    // [B*T, 512]
    int T)
{
    extern __shared__ float sm[];
    float* Wh_sh = sm + OFF_WH;
    float* Wp_sh = sm + OFF_WP;
    float* m_sh  = sm + OFF_M;
    float* h_sh  = sm + OFF_H;
    float* g_sh  = sm + OFF_G;
    float* c_sh  = sm + OFF_C;
    float* red   = sm + OFF_R;

    const int tid = threadIdx.x;
    const int blk = blockIdx.x;
    const int u0 = blk * 8;
    const int p0 = blk * 4;

    // load Wh slice: Wh_sh[l][k] with stride 516
    for (int i = tid; i < 512 * 32; i += 256) {
        int k = i >> 5, l = i & 31;
        int g = l >> 3, uu = l & 7;
        Wh_sh[l * 516 + k] = Wh[(size_t)k * 4096 + g * 1024 + u0 + uu];
    }
    // load Wp slice transposed: Wp_sh[pp][u] with stride 1028
    for (int i = tid; i < 4096; i += 256) {
        int u = i >> 2, pp = i & 3;
        Wp_sh[pp * 1028 + u] = Wp[(size_t)u * 512 + p0 + pp];
    }
    if (tid < 64) c_sh[tid] = 0.f;
    __syncthreads();

    for (int t = 0; t < T; ++t) {
        // ---- stage m_{t-1} into SMEM ----
        if (t == 0) {
            for (int i = tid; i < 4096; i += 256) m_sh[i] = 0.f;
        } else {
            for (int i = tid; i < 1024; i += 256) {          // 1024 float4
                int b = i >> 7, kk = i & 127;
                ((float4*)m_sh)[i] =
                    ((const float4*)(seq_out + (size_t)(b * T + t - 1) * 512))[kk];
            }
        }
        __syncthreads();

        // ---- phase A: gates = xg[t] + m @ Wh_slice ----
        {
            const int l = tid & 31, b = tid >> 5;
            const int g = l >> 3, uu = l & 7;
            float acc = xg[(size_t)(b * T + t) * 4096 + g * 1024 + u0 + uu];
            const float4* m4 = (const float4*)(m_sh + b * 512);
            const float4* w4 = (const float4*)(Wh_sh + l * 516);
#pragma unroll 8
            for (int k4 = 0; k4 < 128; ++k4) {
                float4 mv = m4[k4];
                float4 wv = w4[k4];
                acc += mv.x * wv.x + mv.y * wv.y + mv.z * wv.z + mv.w * wv.w;
            }
            g_sh[b * 32 + l] = acc;
        }
        __syncthreads();

        if (tid < 64) {
            int b = tid >> 3, uu = tid & 7;
            float gi = g_sh[b * 32 +  0 + uu];
            float gj = g_sh[b * 32 +  8 + uu];
            float gf = g_sh[b * 32 + 16 + uu];
            float go = g_sh[b * 32 + 24 + uu];
            float c = sigf(gf + 1.0f) * c_sh[tid] + sigf(gi) * tanhf(gj);
            c_sh[tid] = c;
            float h = sigf(go) * tanhf(c);
            g_hbuf[b * 1024 + u0 + uu] = h;
        }
        grid_bar();

        // ---- phase B: m_t = h @ Wp_slice ----
        for (int i = tid; i < 2048; i += 256) {              // 2048 float4
            int b = i >> 8, j = i & 255;
            *(float4*)(h_sh + b * 1028 + j * 4) = ((const float4*)g_hbuf)[i];
        }
        __syncthreads();
        {
            const int pp = tid & 3, b = (tid >> 2) & 7, ks = tid >> 5;
            const float4* h4 = (const float4*)(h_sh + b * 1028 + ks * 128);
            const float4* w4 = (const float4*)(Wp_sh + pp * 1028 + ks * 128);
            float acc = 0.f;
#pragma unroll
            for (int k4 = 0; k4 < 32; ++k4) {
                float4 hv = h4[k4];
                float4 wv = w4[k4];
                acc += hv.x * wv.x + hv.y * wv.y + hv.z * wv.z + hv.w * wv.w;
            }
            red[ks * 32 + (tid & 31)] = acc;
        }
        __syncthreads();
        if (tid < 32) {
            float s = 0.f;
#pragma unroll
            for (int ks = 0; ks < 8; ++ks) s += red[ks * 32 + tid];
            int pp = tid & 3, b = tid >> 2;
            seq_out[(size_t)(b * T + t) * 512 + p0 + pp] = s;
        }
        grid_bar();
    }
}

// -------------------- joint: out = tanh(ej[b,t] + gj[b,u]) ------------------
// grid.x = B*T*(U/4); block 256 = 4 u-slots x 64 float4 of v.
__global__ __launch_bounds__(256) void joint_kernel(
    const float* __restrict__ ej,   // [B*T, 256] (includes bias)
    const float* __restrict__ gj,   // [B*U, 256]
    float* __restrict__ out)        // [B, T, U, 256]
{
    const int idx = blockIdx.x;
    const int u4 = idx & 15;           // U/4 groups
    const int bt = idx >> 4;           // b*T + t
    const int b  = bt >> 8;            // T = 256
    const int tid = threadIdx.x;
    const int v4 = tid & 63, us = tid >> 6;
    const int u = u4 * 4 + us;

    float4 e4 = ((const float4*)(ej + (size_t)bt * 256))[v4];
    float4 g4 = ((const float4*)(gj + (size_t)(b * Uu + u) * 256))[v4];
    float4 r;
    r.x = tanhf(e4.x + g4.x);
    r.y = tanhf(e4.y + g4.y);
    r.z = tanhf(e4.z + g4.z);
    r.w = tanhf(e4.w + g4.w);
    ((float4*)(out + ((size_t)bt * Uu + u) * 256))[v4] = r;
}

// -------------------- host launch -------------------------------------------
static void run_gemm(const float* A, const float* W, const float* bias,
                     float* C, int n, int K, int N)
{
    dim3 grid(N / 64, n / 64);
    gemm_bias_kernel<<<grid, 256>>>(A, W, bias, C, n, K, N);
}

extern "C" void kernel_launch(void* const* d_in, const int* in_sizes, int n_in,
                              void* d_out, int out_size)
{
    const float* x         = (const float*)d_in[0];   // [8,256,80]
    const float* prev_pred = (const float*)d_in[1];   // [8,64,256]
    const float* enc_Wx0 = (const float*)d_in[2];
    const float* enc_Wh0 = (const float*)d_in[3];
    const float* enc_b0  = (const float*)d_in[4];
    const float* enc_Wp0 = (const float*)d_in[5];
    const float* enc_Wx1 = (const float*)d_in[6];
    const float* enc_Wh1 = (const float*)d_in[7];
    const float* enc_b1  = (const float*)d_in[8];
    const float* enc_Wp1 = (const float*)d_in[9];
    const float* dec_Wx0 = (const float*)d_in[10];
    const float* dec_Wh0 = (const float*)d_in[11];
    const float* dec_b0  = (const float*)d_in[12];
    const float* dec_Wp0 = (const float*)d_in[13];
    const float* dec_Wx1 = (const float*)d_in[14];
    const float* dec_Wh1 = (const float*)d_in[15];
    const float* dec_b1  = (const float*)d_in[16];
    const float* dec_Wp1 = (const float*)d_in[17];
    const float* joint_W = (const float*)d_in[18];
    const float* joint_b = (const float*)d_in[19];
    float* out = (float*)d_out;

    static bool attr_done = false;
    if (!attr_done) {
        cudaFuncSetAttribute(lstm_layer_kernel,
                             cudaFuncAttributeMaxDynamicSharedMemorySize,
                             SMEM_BYTES);
        attr_done = true;
    }

    float* xg;   cudaGetSymbolAddress((void**)&xg,   g_xg);
    float* e0;   cudaGetSymbolAddress((void**)&e0,   g_enc0);
    float* e1;   cudaGetSymbolAddress((void**)&e1,   g_enc1);
    float* dd0;  cudaGetSymbolAddress((void**)&dd0,  g_dec0);
    float* dd1;  cudaGetSymbolAddress((void**)&dd1,  g_dec1);
    float* ej;   cudaGetSymbolAddress((void**)&ej,   g_ej);
    float* gj;   cudaGetSymbolAddress((void**)&gj,   g_gj);

    // ---------------- encoder ----------------
    run_gemm(x, enc_Wx0, enc_b0, xg, Bb * Tt, 80, G4);
    lstm_layer_kernel<<<NBLK, 256, SMEM_BYTES>>>(xg, enc_Wh0, enc_Wp0, e0, Tt);

    run_gemm(e0, enc_Wx1, enc_b1, xg, Bb * Tt, Pp, G4);
    lstm_layer_kernel<<<NBLK, 256, SMEM_BYTES>>>(xg, enc_Wh1, enc_Wp1, e1, Tt);

    // ---------------- decoder ----------------
    run_gemm(prev_pred, dec_Wx0, dec_b0, xg, Bb * Uu, 256, G4);
    lstm_layer_kernel<<<NBLK, 256, SMEM_BYTES>>>(xg, dec_Wh0, dec_Wp0, dd0, Uu);

    run_gemm(dd0, dec_Wx1, dec_b1, xg, Bb * Uu, Pp, G4);
    lstm_layer_kernel<<<NBLK, 256, SMEM_BYTES>>>(xg, dec_Wh1, dec_Wp1, dd1, Uu);

    // ---------------- joint ----------------
    run_gemm(e1,  joint_W, joint_b, ej, Bb * Tt, Pp, Vv);
    run_gemm(dd1, joint_W, nullptr, gj, Bb * Uu, Pp, Vv);

    joint_kernel<<<Bb * Tt * (Uu / 4), 256>>>(ej, gj, out);
}

// round 5
// speedup vs baseline: 1.1377x; 1.1377x over previous
#include <cuda_runtime.h>
#include <cuda_bf16.h>
#include <cstdint>

// ---------------------------------------------------------------------------
// RNN-Transducer: 2x proj-LSTM encoder + 2x proj-LSTM decoder + joint tanh.
// B=8, T=256, U=64, D_enc=80, D_dec=256, H=1024, P=512, V=256.
// ---------------------------------------------------------------------------

#define Bb   8
#define Tt   256
#define Uu   64
#define Hh   1024
#define Pp   512
#define G4   4096
#define Vv   256
#define NBLK 128

// -------------------- scratch (device globals; no allocation) --------------
__device__ float g_xg  [2048 * 4096];      // gate preacts for current layer
__device__ float g_enc0[2048 * 512];
__device__ float g_enc1[2048 * 512];
__device__ float g_dec0[512  * 512];
__device__ float g_dec1[512  * 512];
__device__ float g_ej  [2048 * 256];
__device__ float g_gj  [512  * 256];
__device__ float g_hbuf[8 * 1024];

// -------------------- grid barrier (generation counter) --------------------
__device__ unsigned g_bar_cnt = 0;
__device__ volatile unsigned g_bar_gen = 0;

__device__ __forceinline__ void grid_bar() {
    __syncthreads();
    if (threadIdx.x == 0) {
        __threadfence();
        unsigned gen = g_bar_gen;
        if (atomicAdd(&g_bar_cnt, 1u) == NBLK - 1) {
            g_bar_cnt = 0;
            __threadfence();
            g_bar_gen = gen + 1;
        } else {
            while (g_bar_gen == gen) { __nanosleep(32); }
            __threadfence();
        }
    }
    __syncthreads();
}

__device__ __forceinline__ float sigf(float x) {
    return 1.0f / (1.0f + __expf(-x));
}

// -------------------- generic GEMM: C[n,N] = A[n,K] @ W[K,N] (+bias) -------
// Requires n%64==0, K%16==0, N%64==0 (true for all calls here).
__global__ __launch_bounds__(256) void gemm_bias_kernel(
    const float* __restrict__ A, const float* __restrict__ W,
    const float* __restrict__ bias, float* __restrict__ C,
    int n, int K, int N)
{
    __shared__ float As[16][68];   // [k][m], padded, 4-aligned rows
    __shared__ float Ws[16][64];   // [k][n]
    const int bn = blockIdx.x * 64;
    const int bm = blockIdx.y * 64;
    const int tid = threadIdx.x;
    const int tm = tid >> 4, tn = tid & 15;

    float acc[4][4];
#pragma unroll
    for (int x = 0; x < 4; ++x)
#pragma unroll
        for (int y = 0; y < 4; ++y) acc[x][y] = 0.f;

    for (int k0 = 0; k0 < K; k0 += 16) {
#pragma unroll
        for (int i = tid; i < 1024; i += 256) {
            int r = i >> 4, c = i & 15;                   // r: row in tile, c: k
            As[c][r] = A[(size_t)(bm + r) * K + k0 + c];
        }
#pragma unroll
        for (int i = tid; i < 1024; i += 256) {
            int r = i >> 6, c = i & 63;                   // r: k, c: col in tile
            Ws[r][c] = W[(size_t)(k0 + r) * N + bn + c];
        }
        __syncthreads();
#pragma unroll
        for (int kk = 0; kk < 16; ++kk) {
            const float4 a4 = *(const float4*)&As[kk][tm * 4];
            const float4 b4 = *(const float4*)&Ws[kk][tn * 4];
            const float a[4] = {a4.x, a4.y, a4.z, a4.w};
            const float b[4] = {b4.x, b4.y, b4.z, b4.w};
#pragma unroll
            for (int x = 0; x < 4; ++x)
#pragma unroll
                for (int y = 0; y < 4; ++y) acc[x][y] += a[x] * b[y];
        }
        __syncthreads();
    }

    float bv[4];
#pragma unroll
    for (int y = 0; y < 4; ++y) bv[y] = bias ? bias[bn + tn * 4 + y] : 0.f;
#pragma unroll
    for (int x = 0; x < 4; ++x) {
        size_t row = (size_t)(bm + tm * 4 + x);
#pragma unroll
        for (int y = 0; y < 4; ++y)
            C[row * N + bn + tn * 4 + y] = acc[x][y] + bv[y];
    }
}

// -------------------- persistent projected-LSTM layer -----------------------
// Block blk owns h-units [blk*8, blk*8+8) and p-cols [blk*4, blk*4+4).
// SMEM layout (floats):
//   Wh_sh [32][516]  gatecol-major, k contiguous (stride 516)     16512
//   Wp_sh [4][1028]  p-major, u contiguous (stride 1028)           4112
//   m_sh  [8][512]                                                 4096
//   g_sh  [8][32]                                                   256
//   c_sh  [64]                                                       64
//   red2  [8 b][8 ks][32 l]                                        2048
constexpr int OFF_WH = 0;
constexpr int OFF_WP = OFF_WH + 32 * 516;        // 16512
constexpr int OFF_M  = OFF_WP + 4 * 1028;        // 20624
constexpr int OFF_G  = OFF_M  + 8 * 512;         // 24720
constexpr int OFF_C  = OFF_G  + 256;             // 24976
constexpr int OFF_R  = OFF_C  + 64;              // 25040
constexpr int SMEM_FLOATS = OFF_R + 2048;        // 27088
constexpr int SMEM_BYTES  = SMEM_FLOATS * 4;     // 108,352 B

__global__ __launch_bounds__(256, 1) void lstm_layer_kernel(
    const float* __restrict__ xg,   // [B*T, 4096]
    const float* __restrict__ Wh,   // [512, 4096]
    const float* __restrict__ Wp,   // [1024, 512]
    float* __restrict__ seq_out,    // [B*T, 512]
    int T)
{
    extern __shared__ float sm[];
    float* Wh_sh = sm + OFF_WH;
    float* Wp_sh = sm + OFF_WP;
    float* m_sh  = sm + OFF_M;
    float* g_sh  = sm + OFF_G;
    float* c_sh  = sm + OFF_C;
    float* red2  = sm + OFF_R;

    const int tid = threadIdx.x;
    const int blk = blockIdx.x;
    const int u0 = blk * 8;
    const int p0 = blk * 4;
    const int lane = tid & 31;
    const int wid  = tid >> 5;

    // load Wh slice: Wh_sh[l*516 + k] ; l = 4 gates x 8 units
    for (int i = tid; i < 512 * 32; i += 256) {
        int k = i >> 5, l = i & 31;
        int g = l >> 3, uu = l & 7;
        Wh_sh[l * 516 + k] = Wh[(size_t)k * 4096 + g * 1024 + u0 + uu];
    }
    // load Wp slice transposed: Wp_sh[pp*1028 + u]
    for (int i = tid; i < 4096; i += 256) {
        int u = i >> 2, pp = i & 3;
        Wp_sh[pp * 1028 + u] = Wp[(size_t)u * 512 + p0 + pp];
    }
    if (tid < 64) c_sh[tid] = 0.f;
    __syncthreads();

    for (int t = 0; t < T; ++t) {
        // ---- stage m_{t-1} into SMEM ----
        if (t == 0) {
            for (int i = tid; i < 4096; i += 256) m_sh[i] = 0.f;
        } else {
            for (int i = tid; i < 1024; i += 256) {          // 1024 float4
                int b = i >> 7, kk = i & 127;
                ((float4*)m_sh)[i] =
                    ((const float4*)(seq_out + (size_t)(b * T + t - 1) * 512))[kk];
            }
        }
        __syncthreads();

        // ---- phase A: gates = xg[t] + m @ Wh_slice -------------------------
        // warp wid owns k-chunk [wid*64, wid*64+64); lane = gate-col l.
        // Each Wh float4 load feeds all 8 batches (8 indep accumulators).
        {
            float acc[8];
#pragma unroll
            for (int b = 0; b < 8; ++b) acc[b] = 0.f;
            const float4* w4 = (const float4*)(Wh_sh + lane * 516) + wid * 16;
            const float4* m4 = (const float4*)m_sh + wid * 16;
#pragma unroll
            for (int k4 = 0; k4 < 16; ++k4) {
                const float4 wv = w4[k4];
#pragma unroll
                for (int b = 0; b < 8; ++b) {
                    const float4 mv = m4[b * 128 + k4];     // warp broadcast
                    acc[b] = fmaf(mv.x, wv.x,
                             fmaf(mv.y, wv.y,
                             fmaf(mv.z, wv.z,
                             fmaf(mv.w, wv.w, acc[b]))));
                }
            }
#pragma unroll
            for (int b = 0; b < 8; ++b)
                red2[b * 256 + wid * 32 + lane] = acc[b];   // conflict-free
        }
        __syncthreads();
        {   // reduce 8 k-chunks; thread = (b, l)
            const int b = tid >> 5, l = tid & 31;
            const int g = l >> 3, uu = l & 7;
            float s = xg[(size_t)(b * T + t) * 4096 + g * 1024 + u0 + uu];
            const float* rp = red2 + b * 256 + l;
#pragma unroll
            for (int ks = 0; ks < 8; ++ks) s += rp[ks * 32];
            g_sh[b * 32 + l] = s;
        }
        __syncthreads();

        if (tid < 64) {
            int b = tid >> 3, uu = tid & 7;
            float gi = g_sh[b * 32 +  0 + uu];
            float gj = g_sh[b * 32 +  8 + uu];
            float gf = g_sh[b * 32 + 16 + uu];
            float go = g_sh[b * 32 + 24 + uu];
            float c = sigf(gf + 1.0f) * c_sh[tid] + sigf(gi) * tanhf(gj);
            c_sh[tid] = c;
            float h = sigf(go) * tanhf(c);
            g_hbuf[b * 1024 + u0 + uu] = h;
        }
        grid_bar();

        // ---- phase B: m_t = h @ Wp_slice (h read straight from L2) --------
        {
            const int pp = tid & 3, b = (tid >> 2) & 7, ks = tid >> 5;
            const float4* h4 = (const float4*)g_hbuf + b * 256 + ks * 32;
            const float4* w4 = (const float4*)(Wp_sh + pp * 1028) + ks * 32;
            float acc0 = 0.f, acc1 = 0.f;
#pragma unroll
            for (int k4 = 0; k4 < 32; k4 += 2) {
                const float4 hv0 = h4[k4],     wv0 = w4[k4];
                const float4 hv1 = h4[k4 + 1], wv1 = w4[k4 + 1];
                acc0 = fmaf(hv0.x, wv0.x, fmaf(hv0.y, wv0.y,
                       fmaf(hv0.z, wv0.z, fmaf(hv0.w, wv0.w, acc0))));
                acc1 = fmaf(hv1.x, wv1.x, fmaf(hv1.y, wv1.y,
                       fmaf(hv1.z, wv1.z, fmaf(hv1.w, wv1.w, acc1))));
            }
            red2[ks * 32 + (tid & 31)] = acc0 + acc1;       // conflict-free
        }
        __syncthreads();
        if (tid < 32) {
            float s = 0.f;
#pragma unroll
            for (int ks = 0; ks < 8; ++ks) s += red2[ks * 32 + tid];
            int pp = tid & 3, b = tid >> 2;
            seq_out[(size_t)(b * T + t) * 512 + p0 + pp] = s;
        }
        grid_bar();
    }
}

// -------------------- joint: out = tanh(ej[b,t] + gj[b,u]) ------------------
// grid.x = B*T*(U/4); block 256 = 4 u-slots x 64 float4 of v.
__global__ __launch_bounds__(256) void joint_kernel(
    const float* __restrict__ ej,   // [B*T, 256] (includes bias)
    const float* __restrict__ gj,   // [B*U, 256]
    float* __restrict__ out)        // [B, T, U, 256]
{
    const int idx = blockIdx.x;
    const int u4 = idx & 15;           // U/4 groups
    const int bt = idx >> 4;           // b*T + t
    const int b  = bt >> 8;            // T = 256
    const int tid = threadIdx.x;
    const int v4 = tid & 63, us = tid >> 6;
    const int u = u4 * 4 + us;

    float4 e4 = ((const float4*)(ej + (size_t)bt * 256))[v4];
    float4 g4 = ((const float4*)(gj + (size_t)(b * Uu + u) * 256))[v4];
    float4 r;
    r.x = tanhf(e4.x + g4.x);
    r.y = tanhf(e4.y + g4.y);
    r.z = tanhf(e4.z + g4.z);
    r.w = tanhf(e4.w + g4.w);
    ((float4*)(out + ((size_t)bt * Uu + u) * 256))[v4] = r;
}

// -------------------- host launch -------------------------------------------
static void run_gemm(const float* A, const float* W, const float* bias,
                     float* C, int n, int K, int N)
{
    dim3 grid(N / 64, n / 64);
    gemm_bias_kernel<<<grid, 256>>>(A, W, bias, C, n, K, N);
}

extern "C" void kernel_launch(void* const* d_in, const int* in_sizes, int n_in,
                              void* d_out, int out_size)
{
    const float* x         = (const float*)d_in[0];   // [8,256,80]
    const float* prev_pred = (const float*)d_in[1];   // [8,64,256]
    const float* enc_Wx0 = (const float*)d_in[2];
    const float* enc_Wh0 = (const float*)d_in[3];
    const float* enc_b0  = (const float*)d_in[4];
    const float* enc_Wp0 = (const float*)d_in[5];
    const float* enc_Wx1 = (const float*)d_in[6];
    const float* enc_Wh1 = (const float*)d_in[7];
    const float* enc_b1  = (const float*)d_in[8];
    const float* enc_Wp1 = (const float*)d_in[9];
    const float* dec_Wx0 = (const float*)d_in[10];
    const float* dec_Wh0 = (const float*)d_in[11];
    const float* dec_b0  = (const float*)d_in[12];
    const float* dec_Wp0 = (const float*)d_in[13];
    const float* dec_Wx1 = (const float*)d_in[14];
    const float* dec_Wh1 = (const float*)d_in[15];
    const float* dec_b1  = (const float*)d_in[16];
    const float* dec_Wp1 = (const float*)d_in[17];
    const float* joint_W = (const float*)d_in[18];
    const float* joint_b = (const float*)d_in[19];
    float* out = (float*)d_out;

    static bool attr_done = false;
    if (!attr_done) {
        cudaFuncSetAttribute(lstm_layer_kernel,
                             cudaFuncAttributeMaxDynamicSharedMemorySize,
                             SMEM_BYTES);
        attr_done = true;
    }

    float* xg;   cudaGetSymbolAddress((void**)&xg,   g_xg);
    float* e0;   cudaGetSymbolAddress((void**)&e0,   g_enc0);
    float* e1;   cudaGetSymbolAddress((void**)&e1,   g_enc1);
    float* dd0;  cudaGetSymbolAddress((void**)&dd0,  g_dec0);
    float* dd1;  cudaGetSymbolAddress((void**)&dd1,  g_dec1);
    float* ej;   cudaGetSymbolAddress((void**)&ej,   g_ej);
    float* gj;   cudaGetSymbolAddress((void**)&gj,   g_gj);

    // ---------------- encoder ----------------
    run_gemm(x, enc_Wx0, enc_b0, xg, Bb * Tt, 80, G4);
    lstm_layer_kernel<<<NBLK, 256, SMEM_BYTES>>>(xg, enc_Wh0, enc_Wp0, e0, Tt);

    run_gemm(e0, enc_Wx1, enc_b1, xg, Bb * Tt, Pp, G4);
    lstm_layer_kernel<<<NBLK, 256, SMEM_BYTES>>>(xg, enc_Wh1, enc_Wp1, e1, Tt);

    // ---------------- decoder ----------------
    run_gemm(prev_pred, dec_Wx0, dec_b0, xg, Bb * Uu, 256, G4);
    lstm_layer_kernel<<<NBLK, 256, SMEM_BYTES>>>(xg, dec_Wh0, dec_Wp0, dd0, Uu);

    run_gemm(dd0, dec_Wx1, dec_b1, xg, Bb * Uu, Pp, G4);
    lstm_layer_kernel<<<NBLK, 256, SMEM_BYTES>>>(xg, dec_Wh1, dec_Wp1, dd1, Uu);

    // ---------------- joint ----------------
    run_gemm(e1,  joint_W, joint_b, ej, Bb * Tt, Pp, Vv);
    run_gemm(dd1, joint_W, nullptr, gj, Bb * Uu, Pp, Vv);

    joint_kernel<<<Bb * Tt * (Uu / 4), 256>>>(ej, gj, out);
}

// round 6
// speedup vs baseline: 1.2096x; 1.0632x over previous
#include <cuda_runtime.h>
#include <cuda_bf16.h>
#include <cstdint>

// ---------------------------------------------------------------------------
// RNN-Transducer: 2x proj-LSTM encoder + 2x proj-LSTM decoder + joint tanh.
// B=8, T=256, U=64, D_enc=80, D_dec=256, H=1024, P=512, V=256.
// ---------------------------------------------------------------------------

#define Bb   8
#define Tt   256
#define Uu   64
#define Hh   1024
#define Pp   512
#define G4   4096
#define Vv   256
#define NBLK 128

// -------------------- scratch (device globals; no allocation) --------------
__device__ float g_xg  [2048 * 4096];      // gate preacts for current layer
__device__ float g_enc0[2048 * 512];
__device__ float g_enc1[2048 * 512];
__device__ float g_dec0[512  * 512];
__device__ float g_dec1[512  * 512];
__device__ float g_ej  [2048 * 256];
__device__ float g_gj  [512  * 256];
__device__ float g_hbuf[8 * 1024];

// -------------------- grid barrier (acq/rel generation counter) ------------
// Same protocol as cooperative_groups grid.sync: arrival via release-atomic
// (orders the block's prior global stores, which happen-before via the
// preceding __syncthreads), release store of the new generation by the last
// arriver, acquire-load poll by everyone else. Monotone generation survives
// graph replay; counter self-resets before the release store.
__device__ unsigned g_bar_cnt = 0;
__device__ unsigned g_bar_gen = 0;

__device__ __forceinline__ void grid_bar() {
    __syncthreads();
    if (threadIdx.x == 0) {
        unsigned gen;
        asm volatile("ld.relaxed.gpu.global.u32 %0, [%1];"
                     : "=r"(gen) : "l"(&g_bar_gen));
        unsigned old;
        asm volatile("atom.release.gpu.global.add.u32 %0, [%1], %2;"
                     : "=r"(old) : "l"(&g_bar_cnt), "r"(1u));
        if (old == NBLK - 1) {
            asm volatile("st.relaxed.gpu.global.u32 [%0], %1;"
                         :: "l"(&g_bar_cnt), "r"(0u));
            asm volatile("st.release.gpu.global.u32 [%0], %1;"
                         :: "l"(&g_bar_gen), "r"(gen + 1u));
        } else {
            unsigned cur;
            do {
                asm volatile("ld.acquire.gpu.global.u32 %0, [%1];"
                             : "=r"(cur) : "l"(&g_bar_gen));
            } while (cur == gen);
        }
    }
    __syncthreads();
}

__device__ __forceinline__ float sigf(float x) {
    return 1.0f / (1.0f + __expf(-x));
}

// -------------------- generic GEMM: C[n,N] = A[n,K] @ W[K,N] (+bias) -------
// Requires n%64==0, K%16==0, N%64==0 (true for all calls here).
__global__ __launch_bounds__(256) void gemm_bias_kernel(
    const float* __restrict__ A, const float* __restrict__ W,
    const float* __restrict__ bias, float* __restrict__ C,
    int n, int K, int N)
{
    __shared__ float As[16][68];   // [k][m], padded, 4-aligned rows
    __shared__ float Ws[16][64];   // [k][n]
    const int bn = blockIdx.x * 64;
    const int bm = blockIdx.y * 64;
    const int tid = threadIdx.x;
    const int tm = tid >> 4, tn = tid & 15;

    float acc[4][4];
#pragma unroll
    for (int x = 0; x < 4; ++x)
#pragma unroll
        for (int y = 0; y < 4; ++y) acc[x][y] = 0.f;

    for (int k0 = 0; k0 < K; k0 += 16) {
#pragma unroll
        for (int i = tid; i < 1024; i += 256) {
            int r = i >> 4, c = i & 15;                   // r: row in tile, c: k
            As[c][r] = A[(size_t)(bm + r) * K + k0 + c];
        }
#pragma unroll
        for (int i = tid; i < 1024; i += 256) {
            int r = i >> 6, c = i & 63;                   // r: k, c: col in tile
            Ws[r][c] = W[(size_t)(k0 + r) * N + bn + c];
        }
        __syncthreads();
#pragma unroll
        for (int kk = 0; kk < 16; ++kk) {
            const float4 a4 = *(const float4*)&As[kk][tm * 4];
            const float4 b4 = *(const float4*)&Ws[kk][tn * 4];
            const float a[4] = {a4.x, a4.y, a4.z, a4.w};
            const float b[4] = {b4.x, b4.y, b4.z, b4.w};
#pragma unroll
            for (int x = 0; x < 4; ++x)
#pragma unroll
                for (int y = 0; y < 4; ++y) acc[x][y] += a[x] * b[y];
        }
        __syncthreads();
    }

    float bv[4];
#pragma unroll
    for (int y = 0; y < 4; ++y) bv[y] = bias ? bias[bn + tn * 4 + y] : 0.f;
#pragma unroll
    for (int x = 0; x < 4; ++x) {
        size_t row = (size_t)(bm + tm * 4 + x);
#pragma unroll
        for (int y = 0; y < 4; ++y)
            C[row * N + bn + tn * 4 + y] = acc[x][y] + bv[y];
    }
}

// -------------------- persistent projected-LSTM layer -----------------------
// Block blk owns h-units [blk*8, blk*8+8) and p-cols [blk*4, blk*4+4).
// SMEM layout (floats):
//   Wh_sh [32][516]  gatecol-major, k contiguous (stride 516)     16512
//   Wp_sh [4][1028]  p-major, u contiguous (stride 1028)           4112
//   m_sh  [8][512]                                                 4096
//   c_sh  [64]                                                       64
//   red2  [8 b][264]  (phase A partials; stride 264 => b offsets
//                      banks by 8 -> conflict-free reduce reads)   2112
constexpr int OFF_WH = 0;
constexpr int OFF_WP = OFF_WH + 32 * 516;        // 16512
constexpr int OFF_M  = OFF_WP + 4 * 1028;        // 20624
constexpr int OFF_C  = OFF_M  + 8 * 512;         // 24720
constexpr int OFF_R  = OFF_C  + 64;              // 24784
constexpr int SMEM_FLOATS = OFF_R + 8 * 264;     // 26896
constexpr int SMEM_BYTES  = SMEM_FLOATS * 4;     // 107,584 B

__global__ __launch_bounds__(256, 1) void lstm_layer_kernel(
    const float* __restrict__ xg,   // [B*T, 4096]
    const float* __restrict__ Wh,   // [512, 4096]
    const float* __restrict__ Wp,   // [1024, 512]
    float* __restrict__ seq_out,    // [B*T, 512]
    int T)
{
    extern __shared__ float sm[];
    float* Wh_sh = sm + OFF_WH;
    float* Wp_sh = sm + OFF_WP;
    float* m_sh  = sm + OFF_M;
    float* c_sh  = sm + OFF_C;
    float* red2  = sm + OFF_R;

    const int tid = threadIdx.x;
    const int blk = blockIdx.x;
    const int u0 = blk * 8;
    const int p0 = blk * 4;
    const int lane = tid & 31;
    const int wid  = tid >> 5;

    // load Wh slice: Wh_sh[l*516 + k] ; l = 4 gates x 8 units
    for (int i = tid; i < 512 * 32; i += 256) {
        int k = i >> 5, l = i & 31;
        int g = l >> 3, uu = l & 7;
        Wh_sh[l * 516 + k] = Wh[(size_t)k * 4096 + g * 1024 + u0 + uu];
    }
    // load Wp slice transposed: Wp_sh[pp*1028 + u]
    for (int i = tid; i < 4096; i += 256) {
        int u = i >> 2, pp = i & 3;
        Wp_sh[pp * 1028 + u] = Wp[(size_t)u * 512 + p0 + pp];
    }
    if (tid < 64) c_sh[tid] = 0.f;
    __syncthreads();

    for (int t = 0; t < T; ++t) {
        // ---- prefetch xg gate values for the activation threads (tid<64) --
        // Issued first so the 4 LDGs overlap m-staging + phase A compute.
        float xg4[4];
        if (tid < 64) {
            const int b = tid >> 3, uu = tid & 7;
            const float* xp = xg + (size_t)(b * T + t) * 4096 + u0 + uu;
#pragma unroll
            for (int g = 0; g < 4; ++g) xg4[g] = xp[g * 1024];
        }

        // ---- stage m_{t-1} into SMEM ----
        if (t == 0) {
            for (int i = tid; i < 4096; i += 256) m_sh[i] = 0.f;
        } else {
            for (int i = tid; i < 1024; i += 256) {          // 1024 float4
                int b = i >> 7, kk = i & 127;
                ((float4*)m_sh)[i] =
                    ((const float4*)(seq_out + (size_t)(b * T + t - 1) * 512))[kk];
            }
        }
        __syncthreads();

        // ---- phase A: partial gates = m @ Wh_slice -------------------------
        // warp wid owns k-chunk [wid*64, wid*64+64); lane = gate-col l.
        // Each Wh float4 load feeds all 8 batches (8 indep accumulators).
        {
            float acc[8];
#pragma unroll
            for (int b = 0; b < 8; ++b) acc[b] = 0.f;
            const float4* w4 = (const float4*)(Wh_sh + lane * 516) + wid * 16;
            const float4* m4 = (const float4*)m_sh + wid * 16;
#pragma unroll
            for (int k4 = 0; k4 < 16; ++k4) {
                const float4 wv = w4[k4];
#pragma unroll
                for (int b = 0; b < 8; ++b) {
                    const float4 mv = m4[b * 128 + k4];     // warp broadcast
                    acc[b] = fmaf(mv.x, wv.x,
                             fmaf(mv.y, wv.y,
                             fmaf(mv.z, wv.z,
                             fmaf(mv.w, wv.w, acc[b]))));
                }
            }
#pragma unroll
            for (int b = 0; b < 8; ++b)
                red2[b * 264 + wid * 32 + lane] = acc[b];   // conflict-free
        }
        __syncthreads();

        // ---- fused reduce + activation (64 threads) ------------------------
        if (tid < 64) {
            const int b = tid >> 3, uu = tid & 7;
            float s[4];
#pragma unroll
            for (int g = 0; g < 4; ++g) {
                float a = xg4[g];
                const float* rp = red2 + b * 264 + g * 8 + uu;
#pragma unroll
                for (int ks = 0; ks < 8; ++ks) a += rp[ks * 32];
                s[g] = a;
            }
            // gate order: i, j, f, o
            float c = sigf(s[2] + 1.0f) * c_sh[tid] + sigf(s[0]) * tanhf(s[1]);
            c_sh[tid] = c;
            float h = sigf(s[3]) * tanhf(c);
            g_hbuf[b * 1024 + u0 + uu] = h;
        }
        grid_bar();

        // ---- phase B: m_t = h @ Wp_slice (h read straight from L2) --------
        {
            const int pp = tid & 3, b = (tid >> 2) & 7, ks = tid >> 5;
            const float4* h4 = (const float4*)g_hbuf + b * 256 + ks * 32;
            const float4* w4 = (const float4*)(Wp_sh + pp * 1028) + ks * 32;
            float acc0 = 0.f, acc1 = 0.f;
#pragma unroll
            for (int k4 = 0; k4 < 32; k4 += 2) {
                const float4 hv0 = h4[k4],     wv0 = w4[k4];
                const float4 hv1 = h4[k4 + 1], wv1 = w4[k4 + 1];
                acc0 = fmaf(hv0.x, wv0.x, fmaf(hv0.y, wv0.y,
                       fmaf(hv0.z, wv0.z, fmaf(hv0.w, wv0.w, acc0))));
                acc1 = fmaf(hv1.x, wv1.x, fmaf(hv1.y, wv1.y,
                       fmaf(hv1.z, wv1.z, fmaf(hv1.w, wv1.w, acc1))));
            }
            red2[ks * 32 + (tid & 31)] = acc0 + acc1;       // conflict-free
        }
        __syncthreads();
        if (tid < 32) {
            float s = 0.f;
#pragma unroll
            for (int ks = 0; ks < 8; ++ks) s += red2[ks * 32 + tid];
            int pp = tid & 3, b = tid >> 2;
            seq_out[(size_t)(b * T + t) * 512 + p0 + pp] = s;
        }
        grid_bar();
    }
}

// -------------------- joint: out = tanh(ej[b,t] + gj[b,u]) ------------------
// grid.x = B*T*(U/4); block 256 = 4 u-slots x 64 float4 of v.
__global__ __launch_bounds__(256) void joint_kernel(
    const float* __restrict__ ej,   // [B*T, 256] (includes bias)
    const float* __restrict__ gj,   // [B*U, 256]
    float* __restrict__ out)        // [B, T, U, 256]
{
    const int idx = blockIdx.x;
    const int u4 = idx & 15;           // U/4 groups
    const int bt = idx >> 4;           // b*T + t
    const int b  = bt >> 8;            // T = 256
    const int tid = threadIdx.x;
    const int v4 = tid & 63, us = tid >> 6;
    const int u = u4 * 4 + us;

    float4 e4 = ((const float4*)(ej + (size_t)bt * 256))[v4];
    float4 g4 = ((const float4*)(gj + (size_t)(b * Uu + u) * 256))[v4];
    float4 r;
    r.x = tanhf(e4.x + g4.x);
    r.y = tanhf(e4.y + g4.y);
    r.z = tanhf(e4.z + g4.z);
    r.w = tanhf(e4.w + g4.w);
    ((float4*)(out + ((size_t)bt * Uu + u) * 256))[v4] = r;
}

// -------------------- host launch -------------------------------------------
static void run_gemm(const float* A, const float* W, const float* bias,
                     float* C, int n, int K, int N)
{
    dim3 grid(N / 64, n / 64);
    gemm_bias_kernel<<<grid, 256>>>(A, W, bias, C, n, K, N);
}

extern "C" void kernel_launch(void* const* d_in, const int* in_sizes, int n_in,
                              void* d_out, int out_size)
{
    const float* x         = (const float*)d_in[0];   // [8,256,80]
    const float* prev_pred = (const float*)d_in[1];   // [8,64,256]
    const float* enc_Wx0 = (const float*)d_in[2];
    const float* enc_Wh0 = (const float*)d_in[3];
    const float* enc_b0  = (const float*)d_in[4];
    const float* enc_Wp0 = (const float*)d_in[5];
    const float* enc_Wx1 = (const float*)d_in[6];
    const float* enc_Wh1 = (const float*)d_in[7];
    const float* enc_b1  = (const float*)d_in[8];
    const float* enc_Wp1 = (const float*)d_in[9];
    const float* dec_Wx0 = (const float*)d_in[10];
    const float* dec_Wh0 = (const float*)d_in[11];
    const float* dec_b0  = (const float*)d_in[12];
    const float* dec_Wp0 = (const float*)d_in[13];
    const float* dec_Wx1 = (const float*)d_in[14];
    const float* dec_Wh1 = (const float*)d_in[15];
    const float* dec_b1  = (const float*)d_in[16];
    const float* dec_Wp1 = (const float*)d_in[17];
    const float* joint_W = (const float*)d_in[18];
    const float* joint_b = (const float*)d_in[19];
    float* out = (float*)d_out;

    static bool attr_done = false;
    if (!attr_done) {
        cudaFuncSetAttribute(lstm_layer_kernel,
                             cudaFuncAttributeMaxDynamicSharedMemorySize,
                             SMEM_BYTES);
        attr_done = true;
    }

    float* xg;   cudaGetSymbolAddress((void**)&xg,   g_xg);
    float* e0;   cudaGetSymbolAddress((void**)&e0,   g_enc0);
    float* e1;   cudaGetSymbolAddress((void**)&e1,   g_enc1);
    float* dd0;  cudaGetSymbolAddress((void**)&dd0,  g_dec0);
    float* dd1;  cudaGetSymbolAddress((void**)&dd1,  g_dec1);
    float* ej;   cudaGetSymbolAddress((void**)&ej,   g_ej);
    float* gj;   cudaGetSymbolAddress((void**)&gj,   g_gj);

    // ---------------- encoder ----------------
    run_gemm(x, enc_Wx0, enc_b0, xg, Bb * Tt, 80, G4);
    lstm_layer_kernel<<<NBLK, 256, SMEM_BYTES>>>(xg, enc_Wh0, enc_Wp0, e0, Tt);

    run_gemm(e0, enc_Wx1, enc_b1, xg, Bb * Tt, Pp, G4);
    lstm_layer_kernel<<<NBLK, 256, SMEM_BYTES>>>(xg, enc_Wh1, enc_Wp1, e1, Tt);

    // ---------------- decoder ----------------
    run_gemm(prev_pred, dec_Wx0, dec_b0, xg, Bb * Uu, 256, G4);
    lstm_layer_kernel<<<NBLK, 256, SMEM_BYTES>>>(xg, dec_Wh0, dec_Wp0, dd0, Uu);

    run_gemm(dd0, dec_Wx1, dec_b1, xg, Bb * Uu, Pp, G4);
    lstm_layer_kernel<<<NBLK, 256, SMEM_BYTES>>>(xg, dec_Wh1, dec_Wp1, dd1, Uu);

    // ---------------- joint ----------------
    run_gemm(e1,  joint_W, joint_b, ej, Bb * Tt, Pp, Vv);
    run_gemm(dd1, joint_W, nullptr, gj, Bb * Uu, Pp, Vv);

    joint_kernel<<<Bb * Tt * (Uu / 4), 256>>>(ej, gj, out);
}